// round 8
// baseline (speedup 1.0000x reference)
#include <cuda_runtime.h>
#include <cstdint>

// Problem constants
#define BATCH 16
#define NA    3
#define NC    20
#define NATTR 25          // 5 + NC
#define IH    52
#define IW    52
#define HW    2704        // IH*IW
#define NBOX  8112        // NA*HW
#define NPAD  8192
#define TOPK  2048
#define NBLK  (TOPK / 64)
#define STRIDE_F 8.0f

typedef unsigned long long u64;

// Accurate libdevice expf (XLA's f32 exp lowering), immune to --use_fast_math.
extern "C" __device__ float __nv_expf(float);

// Scratch (allocation-free: __device__ globals)
__device__ float g_conf[BATCH][NBOX];
__device__ int   g_cls [BATCH][NBOX];
__device__ u64   g_runA[BATCH][NPAD];
__device__ u64   g_runB[BATCH][NPAD];

// ---------------------------------------------------------------------------
// Bitwise replica of XLA:GPU's tanh (llvm_ir::EmitFastTanh).
// ---------------------------------------------------------------------------
__device__ __forceinline__ float xla_tanhf(float x) {
    float ax = fabsf(x);
    float xc = fminf(fmaxf(x, -7.90531110763549805f), 7.90531110763549805f);
    float x2 = __fmul_rn(xc, xc);
    float p = -2.76076847742355e-16f;
    p = __fmaf_rn(x2, p, 2.00018790482477e-13f);
    p = __fmaf_rn(x2, p, -8.60467152213735e-11f);
    p = __fmaf_rn(x2, p, 5.12229709037114e-08f);
    p = __fmaf_rn(x2, p, 1.48572235717979e-05f);
    p = __fmaf_rn(x2, p, 6.37261928875436e-04f);
    p = __fmaf_rn(x2, p, 4.89352455891786e-03f);
    p = __fmul_rn(xc, p);
    float q = 1.19825839466702e-06f;
    q = __fmaf_rn(x2, q, 1.18534705686654e-04f);
    q = __fmaf_rn(x2, q, 2.26843463243900e-03f);
    q = __fmaf_rn(x2, q, 4.89352518554385e-03f);
    float r = __fdiv_rn(p, q);
    return (ax < 0.0004f) ? x : r;
}

__device__ __forceinline__ float sigmoid_xla(float x) {
    float t = xla_tanhf(__fmul_rn(0.5f, x));
    return __fmaf_rn(0.5f, t, 0.5f);
}

// ---------------------------------------------------------------------------
// Kernel 1: decode (identical math — measured ~20us).
// ---------------------------------------------------------------------------
__global__ void decode_kernel(const float* __restrict__ in,
                              const float* __restrict__ anchors,
                              float* __restrict__ out) {
    __shared__ float s_out[256 * NATTR];

    int t = blockIdx.x * 256 + threadIdx.x;     // grid sized exactly: no tail
    int b = t / NBOX, n = t % NBOX;
    int a = n / HW,   r = n % HW;
    int gy = r / IW,  gx = r % IW;

    const float* base = in + ((size_t)(b * NA + a) * NATTR) * HW + r;
    float t0 = base[0 * HW];
    float t1 = base[1 * HW];
    float t2 = base[2 * HW];
    float t3 = base[3 * HW];
    float t4 = base[4 * HW];

    float aw = __fdiv_rn(anchors[a * 2 + 0], STRIDE_F);
    float ah = __fdiv_rn(anchors[a * 2 + 1], STRIDE_F);

    float sx = sigmoid_xla(t0);
    float sy = sigmoid_xla(t1);
    float bx = __fmul_rn(__fadd_rn(sx, (float)gx), STRIDE_F);
    float by = __fmul_rn(__fadd_rn(sy, (float)gy), STRIDE_F);
    float bw = __fmul_rn(__fmul_rn(__nv_expf(t2), aw), STRIDE_F);
    float bh = __fmul_rn(__fmul_rn(__nv_expf(t3), ah), STRIDE_F);
    float conf = sigmoid_xla(t4);

    float* so = s_out + threadIdx.x * NATTR;
    so[0] = bx; so[1] = by; so[2] = bw; so[3] = bh; so[4] = conf;

    float bestv = -3.402823466e+38f;
    int best = 0;
#pragma unroll
    for (int c = 0; c < NC; c++) {
        float v = sigmoid_xla(base[(5 + c) * HW]);
        so[5 + c] = v;
        if (v > bestv) { bestv = v; best = c; }
    }
    g_conf[b][n] = conf;
    g_cls[b][n]  = best;
    __syncthreads();

    float* oblk = out + (size_t)blockIdx.x * 256 * NATTR;
    for (int k = threadIdx.x; k < 256 * NATTR; k += 256)
        oblk[k] = s_out[k];
}

// ---------------------------------------------------------------------------
// Top-K: truncated tournament merge. key = (conf_bits<<32)|(~idx);
// desc = conf desc then idx asc. Run r sorted DESC iff popcount(r) even.
// ---------------------------------------------------------------------------
__device__ __forceinline__ u64 cex(u64 a, u64 v, bool lower, bool desc) {
    u64 mx = a > v ? a : v;
    u64 mn = a > v ? v : a;
    return desc ? (lower ? mx : mn) : (lower ? mn : mx);
}

// 2a: local sort of 8 x 1024 runs per batch; element register-resident.
__global__ void local_sort(void) {
    __shared__ u64 s[1024];
    int c = blockIdx.x, b = blockIdx.y, t = threadIdx.x;
    int i = c * 1024 + t;
    u64 mine = 0ull;
    if (i < NBOX) {
        unsigned cb = __float_as_uint(g_conf[b][i]);
        mine = ((u64)cb << 32) | (unsigned)(0xFFFFFFFFu - (unsigned)i);
    }
    bool dirDesc = ((__popc(c) & 1) == 0);

    for (int k2 = 2; k2 <= 1024; k2 <<= 1) {
        for (int j = k2 >> 1; j > 0; j >>= 1) {
            bool descb = (((t & k2) == 0) == dirDesc);
            bool lower = (t & j) == 0;
            if (j >= 32) {
                s[t] = mine;
                __syncthreads();
                u64 v = s[t ^ j];
                mine = cex(mine, v, lower, descb);
                __syncthreads();
            } else {
                u64 v = __shfl_xor_sync(0xFFFFFFFFu, mine, j);
                mine = cex(mine, v, lower, descb);
            }
        }
    }
    g_runA[b][c * 1024 + t] = mine;
}

// Descending/ascending bitonic merge of a 2048-element bitonic sequence held
// as (r0 = elem t, r1 = elem t+1024). j=1024 in-register; 512..32 smem; 16..1 shfl.
__device__ __forceinline__ void bitonic_merge_2048(u64& r0, u64& r1,
                                                   u64* s, int t, bool dirDesc) {
    {   // j = 1024: in-thread pair, r0 is lower
        bool sw = dirDesc ? (r0 < r1) : (r0 > r1);
        if (sw) { u64 tmp = r0; r0 = r1; r1 = tmp; }
    }
#pragma unroll
    for (int j = 512; j >= 32; j >>= 1) {
        s[t] = r0; s[t + 1024] = r1;
        __syncthreads();
        u64 v0 = s[t ^ j];
        u64 v1 = s[(t ^ j) + 1024];
        bool lower = (t & j) == 0;
        r0 = cex(r0, v0, lower, dirDesc);
        r1 = cex(r1, v1, lower, dirDesc);
        __syncthreads();
    }
#pragma unroll
    for (int j = 16; j >= 1; j >>= 1) {
        u64 v0 = __shfl_xor_sync(0xFFFFFFFFu, r0, j);
        u64 v1 = __shfl_xor_sync(0xFFFFFFFFu, r1, j);
        bool lower = (t & j) == 0;
        r0 = cex(r0, v0, lower, dirDesc);
        r1 = cex(r1, v1, lower, dirDesc);
    }
}

// 2b: merge pass. RUNLEN=1024: full merge 2x1024 -> 2048.
//     RUNLEN=2048: truncating merge 2x2048 -> top 2048 (bitonic split).
template<int RUNLEN, int SRCA>
__global__ void merge_pass(void) {
    __shared__ u64 s[2048];
    int m = blockIdx.x, b = blockIdx.y, t = threadIdx.x;
    const u64* in = SRCA ? g_runA[b] : g_runB[b];
    u64* outp     = SRCA ? g_runB[b] : g_runA[b];
    const u64* A  = in + 2 * m * RUNLEN;
    const u64* Bp = A + RUNLEN;
    bool dirDesc = ((__popc(m) & 1) == 0);

    u64 r0, r1;
    if (RUNLEN == 1024) {
        r0 = A[t];                 // element t
        r1 = Bp[t];                // element t+1024
    } else {
        u64 a0 = A[t],        b0 = Bp[t];
        u64 a1 = A[t + 1024], b1 = Bp[t + 1024];
        r0 = a0 > b0 ? a0 : b0;    // bitonic split: top half
        r1 = a1 > b1 ? a1 : b1;
    }
    bitonic_merge_2048(r0, r1, s, t, dirDesc);
    outp[m * 2048 + t]        = r0;
    outp[m * 2048 + 1024 + t] = r1;
}

// ---------------------------------------------------------------------------
// Kernel 3: fused final-merge + prep + on-demand NMS. One CTA per batch,
// 1024 threads. Suppression rows computed only for KEPT boxes (on demand).
// ---------------------------------------------------------------------------
__global__ void nms_fused(const float* __restrict__ out,
                          float* __restrict__ out_topidx,
                          float* __restrict__ keep_out) {
    extern __shared__ unsigned char dyn[];
    u64*   keys = (u64*)dyn;                        // [2048]  16384 B
    float* sx1  = (float*)(dyn + 16384);            // [2048]
    float* sy1  = sx1 + 2048;
    float* sx2  = sy1 + 2048;
    float* sy2  = sx2 + 2048;
    float* sar  = sy2 + 2048;
    short* scl  = (short*)(sar + 2048);             // [2048]
    u64*   diag = (u64*)(scl + 2048);               // [64]
    u64*   keepA = diag + 64;                       // [32]
    unsigned* rem32 = (unsigned*)(keepA + 32);      // [64]
    unsigned* vab32 = rem32 + 64;                   // [64]

    int b = blockIdx.x, t = threadIdx.x;
    if (t < 64) { rem32[t] = 0u; vab32[t] = 0u; }

    // ---- final truncating merge (desc): runA = [2048 desc | 2048 asc] ----
    const u64* A  = g_runA[b];
    const u64* Bp = A + 2048;
    u64 a0 = A[t],        b0 = Bp[t];
    u64 a1 = A[t + 1024], b1 = Bp[t + 1024];
    u64 r0 = a0 > b0 ? a0 : b0;
    u64 r1 = a1 > b1 ? a1 : b1;
    bitonic_merge_2048(r0, r1, keys, t, true);

    // ---- fused prep into smem ----
#pragma unroll
    for (int q = 0; q < 2; q++) {
        int i = t + q * 1024;
        u64 kk = q ? r1 : r0;
        int n = (int)(0xFFFFFFFFu - (unsigned)(kk & 0xFFFFFFFFull));
        out_topidx[b * TOPK + i] = (float)n;

        const float* o = out + ((size_t)b * NBOX + n) * NATTR;
        float cx = o[0], cy = o[1], w = o[2], h = o[3];
        float conf = __uint_as_float((unsigned)(kk >> 32));
        float hw2 = __fmul_rn(w, 0.5f);
        float hh2 = __fmul_rn(h, 0.5f);
        float x1 = __fsub_rn(cx, hw2);
        float y1 = __fsub_rn(cy, hh2);
        float x2 = __fadd_rn(cx, hw2);
        float y2 = __fadd_rn(cy, hh2);
        sx1[i] = x1; sy1[i] = y1; sx2[i] = x2; sy2[i] = y2;
        sar[i] = __fmul_rn(__fadd_rn(__fsub_rn(x2, x1), 1.0f),
                           __fadd_rn(__fsub_rn(y2, y1), 1.0f));
        scl[i] = (short)g_cls[b][n];
        if (conf >= 0.5f)
            atomicOr(&vab32[i >> 5], 1u << (i & 31));
    }
    __syncthreads();

    // ---- block-greedy NMS with on-demand suppression ----
    for (int bk = 0; bk < NBLK; bk++) {
        int j0 = bk * 64;

        // diagonal 64x64 block: thread t<64 computes row (j0+t) vs jj>t
        if (t < 64) {
            int i = j0 + t;
            float xi1 = sx1[i], yi1 = sy1[i], xi2 = sx2[i], yi2 = sy2[i];
            float ai = sar[i];
            short ci = scl[i];
            u64 bits = 0ull;
            for (int jj = t + 1; jj < 64; jj++) {
                int jg = j0 + jj;
                if (scl[jg] != ci) continue;
                float ix1 = fmaxf(xi1, sx1[jg]);
                float iy1 = fmaxf(yi1, sy1[jg]);
                float ix2 = fminf(xi2, sx2[jg]);
                float iy2 = fminf(yi2, sy2[jg]);
                float iw = __fadd_rn(__fsub_rn(ix2, ix1), 1.0f); iw = fmaxf(iw, 0.0f);
                float ih = __fadd_rn(__fsub_rn(iy2, iy1), 1.0f); ih = fmaxf(ih, 0.0f);
                float inter = __fmul_rn(iw, ih);
                float den = __fadd_rn(__fsub_rn(__fadd_rn(ai, sar[jg]), inter), 1e-16f);
                float iou = __fdiv_rn(inter, den);
                if (iou >= 0.4f) bits |= 1ull << jj;
            }
            diag[t] = bits;
        }
        __syncthreads();

        // serial greedy resolve of this 64-word (validated in round 6)
        if (t == 0) {
            u64 rem = ((u64)rem32[2 * bk + 1] << 32) | rem32[2 * bk];
            u64 vab = ((u64)vab32[2 * bk + 1] << 32) | vab32[2 * bk];
            u64 cand = vab & ~rem;
            u64 k64 = 0ull;
            while (cand) {
                int u = __ffsll((long long)cand) - 1;
                k64 |= 1ull << u;
                cand &= ~(1ull << u);
                cand &= ~diag[u];
            }
            keepA[bk] = k64;
        }
        __syncthreads();
        u64 k64 = keepA[bk];

        // on-demand cross suppression: kept u in block bk vs later candidates
        if (k64) {
            for (int jg = j0 + 64 + t; jg < TOPK; jg += 1024) {
                short cj = scl[jg];
                float xj1 = sx1[jg], yj1 = sy1[jg];
                float xj2 = sx2[jg], yj2 = sy2[jg], aj = sar[jg];
                u64 kk = k64;
                bool hit = false;
                while (kk) {
                    int u = __ffsll((long long)kk) - 1;
                    kk &= kk - 1;
                    int iu = j0 + u;
                    if (scl[iu] != cj) continue;
                    float ix1 = fmaxf(sx1[iu], xj1);
                    float iy1 = fmaxf(sy1[iu], yj1);
                    float ix2 = fminf(sx2[iu], xj2);
                    float iy2 = fminf(sy2[iu], yj2);
                    float iw = __fadd_rn(__fsub_rn(ix2, ix1), 1.0f); iw = fmaxf(iw, 0.0f);
                    float ih = __fadd_rn(__fsub_rn(iy2, iy1), 1.0f); ih = fmaxf(ih, 0.0f);
                    float inter = __fmul_rn(iw, ih);
                    float den = __fadd_rn(__fsub_rn(__fadd_rn(sar[iu], aj), inter), 1e-16f);
                    float iou = __fdiv_rn(inter, den);
                    if (iou >= 0.4f) { hit = true; break; }
                }
                if (hit) atomicOr(&rem32[jg >> 5], 1u << (jg & 31));
            }
        }
        __syncthreads();
    }

    // ---- write keep ----
#pragma unroll
    for (int q = 0; q < 2; q++) {
        int i = t + q * 1024;
        keep_out[b * TOPK + i] =
            ((keepA[i >> 6] >> (i & 63)) & 1ull) ? 1.0f : 0.0f;
    }
}

#define NMS_FUSED_SMEM (16384 + 5 * 8192 + 4096 + 512 + 256 + 256 + 256)

// ---------------------------------------------------------------------------
// Launch: out = [output(B*NBOX*NATTR) | top_idx(B*TOPK) | keep(B*TOPK)] float32
// ---------------------------------------------------------------------------
extern "C" void kernel_launch(void* const* d_in, const int* in_sizes, int n_in,
                              void* d_out, int out_size) {
    (void)in_sizes; (void)n_in; (void)out_size;
    const float* in      = (const float*)d_in[0];
    const float* anchors = (const float*)d_in[1];
    float* out      = (float*)d_out;
    float* top_out  = out + (size_t)BATCH * NBOX * NATTR;
    float* keep_out = top_out + (size_t)BATCH * TOPK;

    int total = BATCH * NBOX;                 // 129792 = 256 * 507, no tail
    decode_kernel<<<total / 256, 256>>>(in, anchors, out);

    local_sort<<<dim3(8, BATCH), 1024>>>();
    merge_pass<1024, 1><<<dim3(4, BATCH), 1024>>>();   // A -> B (full merges)
    merge_pass<2048, 0><<<dim3(2, BATCH), 1024>>>();   // B -> A (truncating)

    (void)cudaFuncSetAttribute(nms_fused,
                               cudaFuncAttributeMaxDynamicSharedMemorySize,
                               NMS_FUSED_SMEM);
    nms_fused<<<BATCH, 1024, NMS_FUSED_SMEM>>>(out, top_out, keep_out);
}

// round 9
// speedup vs baseline: 5.4071x; 5.4071x over previous
#include <cuda_runtime.h>
#include <cstdint>

// Problem constants
#define BATCH 16
#define NA    3
#define NC    20
#define NATTR 25          // 5 + NC
#define IH    52
#define IW    52
#define HW    2704        // IH*IW
#define NBOX  8112        // NA*HW
#define NPAD  8192
#define TOPK  2048
#define NWORDS (TOPK / 64)    // 32 u64 words per suppression row
#define NBLK   (TOPK / 64)    // 32 blocks of 64 candidates
#define STRIDE_F 8.0f

typedef unsigned long long u64;

// Accurate libdevice expf (XLA's f32 exp lowering), immune to --use_fast_math.
extern "C" __device__ float __nv_expf(float);

// Scratch (allocation-free: __device__ globals)
__device__ float g_conf[BATCH][NBOX];
__device__ int   g_cls [BATCH][NBOX];
__device__ u64   g_runA[BATCH][NPAD];
__device__ u64   g_runB[BATCH][NPAD];

// NMS staging
__device__ float g_x1[BATCH][TOPK];
__device__ float g_y1[BATCH][TOPK];
__device__ float g_x2[BATCH][TOPK];
__device__ float g_y2[BATCH][TOPK];
__device__ float g_ar[BATCH][TOPK];
__device__ short g_cl[BATCH][TOPK];
__device__ u64   g_vab[BATCH][NWORDS];          // validity bitmask
__device__ u64   g_mask[BATCH][TOPK][NWORDS];   // 8 MB suppression matrix

// ---------------------------------------------------------------------------
// Bitwise replica of XLA:GPU's tanh (llvm_ir::EmitFastTanh).
// ---------------------------------------------------------------------------
__device__ __forceinline__ float xla_tanhf(float x) {
    float ax = fabsf(x);
    float xc = fminf(fmaxf(x, -7.90531110763549805f), 7.90531110763549805f);
    float x2 = __fmul_rn(xc, xc);
    float p = -2.76076847742355e-16f;
    p = __fmaf_rn(x2, p, 2.00018790482477e-13f);
    p = __fmaf_rn(x2, p, -8.60467152213735e-11f);
    p = __fmaf_rn(x2, p, 5.12229709037114e-08f);
    p = __fmaf_rn(x2, p, 1.48572235717979e-05f);
    p = __fmaf_rn(x2, p, 6.37261928875436e-04f);
    p = __fmaf_rn(x2, p, 4.89352455891786e-03f);
    p = __fmul_rn(xc, p);
    float q = 1.19825839466702e-06f;
    q = __fmaf_rn(x2, q, 1.18534705686654e-04f);
    q = __fmaf_rn(x2, q, 2.26843463243900e-03f);
    q = __fmaf_rn(x2, q, 4.89352518554385e-03f);
    float r = __fdiv_rn(p, q);
    return (ax < 0.0004f) ? x : r;
}

__device__ __forceinline__ float sigmoid_xla(float x) {
    float t = xla_tanhf(__fmul_rn(0.5f, x));
    return __fmaf_rn(0.5f, t, 0.5f);
}

// ---------------------------------------------------------------------------
// Kernel 1: decode (identical math — measured ~20us).
// ---------------------------------------------------------------------------
__global__ void decode_kernel(const float* __restrict__ in,
                              const float* __restrict__ anchors,
                              float* __restrict__ out) {
    __shared__ float s_out[256 * NATTR];

    int t = blockIdx.x * 256 + threadIdx.x;     // grid sized exactly: no tail
    int b = t / NBOX, n = t % NBOX;
    int a = n / HW,   r = n % HW;
    int gy = r / IW,  gx = r % IW;

    const float* base = in + ((size_t)(b * NA + a) * NATTR) * HW + r;
    float t0 = base[0 * HW];
    float t1 = base[1 * HW];
    float t2 = base[2 * HW];
    float t3 = base[3 * HW];
    float t4 = base[4 * HW];

    float aw = __fdiv_rn(anchors[a * 2 + 0], STRIDE_F);
    float ah = __fdiv_rn(anchors[a * 2 + 1], STRIDE_F);

    float sx = sigmoid_xla(t0);
    float sy = sigmoid_xla(t1);
    float bx = __fmul_rn(__fadd_rn(sx, (float)gx), STRIDE_F);
    float by = __fmul_rn(__fadd_rn(sy, (float)gy), STRIDE_F);
    float bw = __fmul_rn(__fmul_rn(__nv_expf(t2), aw), STRIDE_F);
    float bh = __fmul_rn(__fmul_rn(__nv_expf(t3), ah), STRIDE_F);
    float conf = sigmoid_xla(t4);

    float* so = s_out + threadIdx.x * NATTR;
    so[0] = bx; so[1] = by; so[2] = bw; so[3] = bh; so[4] = conf;

    float bestv = -3.402823466e+38f;
    int best = 0;
#pragma unroll
    for (int c = 0; c < NC; c++) {
        float v = sigmoid_xla(base[(5 + c) * HW]);
        so[5 + c] = v;
        if (v > bestv) { bestv = v; best = c; }
    }
    g_conf[b][n] = conf;
    g_cls[b][n]  = best;
    __syncthreads();

    float* oblk = out + (size_t)blockIdx.x * 256 * NATTR;
    for (int k = threadIdx.x; k < 256 * NATTR; k += 256)
        oblk[k] = s_out[k];
}

// ---------------------------------------------------------------------------
// Top-K: truncated tournament merge. key = (conf_bits<<32)|(~idx);
// desc = conf desc then idx asc. Run r sorted DESC iff popcount(r) even.
// ---------------------------------------------------------------------------
__device__ __forceinline__ u64 cex(u64 a, u64 v, bool lower, bool desc) {
    u64 mx = a > v ? a : v;
    u64 mn = a > v ? v : a;
    return desc ? (lower ? mx : mn) : (lower ? mn : mx);
}

// 2a: local sort of 8 x 1024 runs per batch; element register-resident.
__global__ void local_sort(void) {
    __shared__ u64 s[1024];
    int c = blockIdx.x, b = blockIdx.y, t = threadIdx.x;
    int i = c * 1024 + t;
    u64 mine = 0ull;
    if (i < NBOX) {
        unsigned cb = __float_as_uint(g_conf[b][i]);
        mine = ((u64)cb << 32) | (unsigned)(0xFFFFFFFFu - (unsigned)i);
    }
    bool dirDesc = ((__popc(c) & 1) == 0);

    for (int k2 = 2; k2 <= 1024; k2 <<= 1) {
        for (int j = k2 >> 1; j > 0; j >>= 1) {
            bool descb = (((t & k2) == 0) == dirDesc);
            bool lower = (t & j) == 0;
            if (j >= 32) {
                s[t] = mine;
                __syncthreads();
                u64 v = s[t ^ j];
                mine = cex(mine, v, lower, descb);
                __syncthreads();
            } else {
                u64 v = __shfl_xor_sync(0xFFFFFFFFu, mine, j);
                mine = cex(mine, v, lower, descb);
            }
        }
    }
    g_runA[b][c * 1024 + t] = mine;
}

// Descending/ascending bitonic merge of a 2048-element bitonic sequence held
// as (r0 = elem t, r1 = elem t+1024). j=1024 in-register; 512..32 smem; 16..1 shfl.
__device__ __forceinline__ void bitonic_merge_2048(u64& r0, u64& r1,
                                                   u64* s, int t, bool dirDesc) {
    {   // j = 1024: in-thread pair, r0 is lower
        bool sw = dirDesc ? (r0 < r1) : (r0 > r1);
        if (sw) { u64 tmp = r0; r0 = r1; r1 = tmp; }
    }
#pragma unroll
    for (int j = 512; j >= 32; j >>= 1) {
        s[t] = r0; s[t + 1024] = r1;
        __syncthreads();
        u64 v0 = s[t ^ j];
        u64 v1 = s[(t ^ j) + 1024];
        bool lower = (t & j) == 0;
        r0 = cex(r0, v0, lower, dirDesc);
        r1 = cex(r1, v1, lower, dirDesc);
        __syncthreads();
    }
#pragma unroll
    for (int j = 16; j >= 1; j >>= 1) {
        u64 v0 = __shfl_xor_sync(0xFFFFFFFFu, r0, j);
        u64 v1 = __shfl_xor_sync(0xFFFFFFFFu, r1, j);
        bool lower = (t & j) == 0;
        r0 = cex(r0, v0, lower, dirDesc);
        r1 = cex(r1, v1, lower, dirDesc);
    }
}

// 2b: merge pass. RUNLEN=1024: full merge 2x1024 -> 2048.
//     RUNLEN=2048: truncating merge 2x2048 -> top 2048 (bitonic split).
template<int RUNLEN, int SRCA>
__global__ void merge_pass(void) {
    __shared__ u64 s[2048];
    int m = blockIdx.x, b = blockIdx.y, t = threadIdx.x;
    const u64* in = SRCA ? g_runA[b] : g_runB[b];
    u64* outp     = SRCA ? g_runB[b] : g_runA[b];
    const u64* A  = in + 2 * m * RUNLEN;
    const u64* Bp = A + RUNLEN;
    bool dirDesc = ((__popc(m) & 1) == 0);

    u64 r0, r1;
    if (RUNLEN == 1024) {
        r0 = A[t];                 // element t
        r1 = Bp[t];                // element t+1024
    } else {
        u64 a0 = A[t],        b0 = Bp[t];
        u64 a1 = A[t + 1024], b1 = Bp[t + 1024];
        r0 = a0 > b0 ? a0 : b0;    // bitonic split: top half
        r1 = a1 > b1 ? a1 : b1;
    }
    bitonic_merge_2048(r0, r1, s, t, dirDesc);
    outp[m * 2048 + t]        = r0;
    outp[m * 2048 + 1024 + t] = r1;
}

// 2c: final truncating merge (desc) + fused NMS prep. grid (BATCH), 1024 thr.
__global__ void merge_final(const float* __restrict__ out,
                            float* __restrict__ out_topidx) {
    __shared__ u64 s[2048];
    __shared__ unsigned s_vab32[64];
    int b = blockIdx.x, t = threadIdx.x;
    if (t < 64) s_vab32[t] = 0u;

    const u64* A  = g_runA[b];
    const u64* Bp = A + 2048;
    u64 a0 = A[t],        b0 = Bp[t];
    u64 a1 = A[t + 1024], b1 = Bp[t + 1024];
    u64 r0 = a0 > b0 ? a0 : b0;
    u64 r1 = a1 > b1 ? a1 : b1;
    bitonic_merge_2048(r0, r1, s, t, true);

#pragma unroll
    for (int q = 0; q < 2; q++) {
        int i = t + q * 1024;
        u64 kk = q ? r1 : r0;
        int n = (int)(0xFFFFFFFFu - (unsigned)(kk & 0xFFFFFFFFull));
        out_topidx[b * TOPK + i] = (float)n;

        const float* o = out + ((size_t)b * NBOX + n) * NATTR;
        float cx = o[0], cy = o[1], w = o[2], h = o[3];
        float conf = __uint_as_float((unsigned)(kk >> 32));
        float hw2 = __fmul_rn(w, 0.5f);
        float hh2 = __fmul_rn(h, 0.5f);
        float x1 = __fsub_rn(cx, hw2);
        float y1 = __fsub_rn(cy, hh2);
        float x2 = __fadd_rn(cx, hw2);
        float y2 = __fadd_rn(cy, hh2);
        g_x1[b][i] = x1; g_y1[b][i] = y1; g_x2[b][i] = x2; g_y2[b][i] = y2;
        g_ar[b][i] = __fmul_rn(__fadd_rn(__fsub_rn(x2, x1), 1.0f),
                               __fadd_rn(__fsub_rn(y2, y1), 1.0f));
        g_cl[b][i] = (short)g_cls[b][n];
        if (conf >= 0.5f)
            atomicOr(&s_vab32[i >> 5], 1u << (i & 31));
    }
    __syncthreads();
    if (t < 64) ((unsigned*)g_vab[b])[t] = s_vab32[t];
}

// ---------------------------------------------------------------------------
// Kernel 3: suppression mask (unchanged — measured 19.8us).
// ---------------------------------------------------------------------------
__global__ void nms_mask(void) {
    int jb = blockIdx.x, ib = blockIdx.y, b = blockIdx.z;
    if (jb < ib) return;

    __shared__ float jx1[64], jy1[64], jx2[64], jy2[64], jar[64];
    __shared__ u64 s_cm[NC];

    int t = threadIdx.x;
    int j0 = jb * 64;
    if (t < NC) s_cm[t] = 0ull;
    __syncthreads();
    jx1[t] = g_x1[b][j0 + t];
    jy1[t] = g_y1[b][j0 + t];
    jx2[t] = g_x2[b][j0 + t];
    jy2[t] = g_y2[b][j0 + t];
    jar[t] = g_ar[b][j0 + t];
    atomicOr(&s_cm[g_cl[b][j0 + t]], 1ull << t);
    __syncthreads();

    int i = ib * 64 + t;
    float xi1 = g_x1[b][i], yi1 = g_y1[b][i];
    float xi2 = g_x2[b][i], yi2 = g_y2[b][i];
    float ai  = g_ar[b][i];
    short ci  = g_cl[b][i];

    u64 mm = s_cm[ci];
    if (jb == ib) mm = (t < 63) ? (mm & (~0ull << (t + 1))) : 0ull;

    u64 bits = 0ull;
    while (mm) {
        int jj = __ffsll((long long)mm) - 1;
        mm &= mm - 1;
        float ix1 = fmaxf(xi1, jx1[jj]);
        float iy1 = fmaxf(yi1, jy1[jj]);
        float ix2 = fminf(xi2, jx2[jj]);
        float iy2 = fminf(yi2, jy2[jj]);
        float iw = __fadd_rn(__fsub_rn(ix2, ix1), 1.0f); iw = fmaxf(iw, 0.0f);
        float ih = __fadd_rn(__fsub_rn(iy2, iy1), 1.0f); ih = fmaxf(ih, 0.0f);
        float inter = __fmul_rn(iw, ih);
        float den = __fadd_rn(__fsub_rn(__fadd_rn(ai, jar[jj]), inter), 1e-16f);
        float iou = __fdiv_rn(inter, den);
        if (iou >= 0.4f) bits |= 1ull << jj;
    }
    g_mask[b][i][jb] = bits;
}

// ---------------------------------------------------------------------------
// Kernel 4: block-greedy reduce, lazy-row version. Diagonal words for ALL
// blocks preloaded once (16 KB smem); apply fetches only KEPT rows straight
// from L2 (w-threads coalesce each row into 256B transactions). Greedy
// semantics identical to the round-6/7 passing kernels.
// ---------------------------------------------------------------------------
__global__ void nms_reduce(float* __restrict__ keep_out) {
    __shared__ u64 diagAll[NBLK][64];       // 16 KB
    __shared__ unsigned rem32[64];
    __shared__ u64 s_vab[NWORDS];
    __shared__ u64 keepA[NBLK];

    int b = blockIdx.x, t = threadIdx.x;    // 256 threads
    if (t < 64) rem32[t] = 0u;
    if (t < NWORDS) s_vab[t] = g_vab[b][t];

    // preload all diagonal words: diagAll[bk][u] = g_mask[b][bk*64+u][bk]
    for (int k = t; k < NBLK * 64; k += 256) {
        int bk = k >> 6, u = k & 63;
        diagAll[bk][u] = g_mask[b][bk * 64 + u][bk];
    }
    __syncthreads();

    for (int bk = 0; bk < NBLK; bk++) {
        // serial greedy resolve of this 64-candidate word (validated R6/R7)
        if (t == 0) {
            u64 rem = ((u64)rem32[2 * bk + 1] << 32) | rem32[2 * bk];
            u64 cand = s_vab[bk] & ~rem;
            u64 k64 = 0ull;
            while (cand) {
                int u = __ffsll((long long)cand) - 1;
                k64 |= 1ull << u;
                cand &= ~(1ull << u);
                cand &= ~diagAll[bk][u];    // bits only for j > u
            }
            keepA[bk] = k64;
        }
        __syncthreads();
        u64 k64 = keepA[bk];

        if (t < 64)
            keep_out[b * TOPK + bk * 64 + t] =
                ((k64 >> t) & 1ull) ? 1.0f : 0.0f;

        // lazy apply: thread (w,g) ORs kept rows u (u%8==g) into word w,
        // reading rows directly from L2 (coalesced across w).
        if (k64) {
            int w = t & 31, g = t >> 5;
            if (w > bk) {
                u64 kk = k64 & (0x0101010101010101ull << g);
                u64 part = 0ull;
                while (kk) {
                    int u = __ffsll((long long)kk) - 1;
                    kk &= kk - 1;
                    part |= g_mask[b][bk * 64 + u][w];
                }
                if (part) {
                    unsigned lo = (unsigned)part, hi = (unsigned)(part >> 32);
                    if (lo) atomicOr(&rem32[2 * w],     lo);
                    if (hi) atomicOr(&rem32[2 * w + 1], hi);
                }
            }
        }
        __syncthreads();
    }
}

// ---------------------------------------------------------------------------
// Launch: out = [output(B*NBOX*NATTR) | top_idx(B*TOPK) | keep(B*TOPK)] float32
// ---------------------------------------------------------------------------
extern "C" void kernel_launch(void* const* d_in, const int* in_sizes, int n_in,
                              void* d_out, int out_size) {
    (void)in_sizes; (void)n_in; (void)out_size;
    const float* in      = (const float*)d_in[0];
    const float* anchors = (const float*)d_in[1];
    float* out      = (float*)d_out;
    float* top_out  = out + (size_t)BATCH * NBOX * NATTR;
    float* keep_out = top_out + (size_t)BATCH * TOPK;

    int total = BATCH * NBOX;                 // 129792 = 256 * 507, no tail
    decode_kernel<<<total / 256, 256>>>(in, anchors, out);

    local_sort<<<dim3(8, BATCH), 1024>>>();
    merge_pass<1024, 1><<<dim3(4, BATCH), 1024>>>();   // A -> B (full merges)
    merge_pass<2048, 0><<<dim3(2, BATCH), 1024>>>();   // B -> A (truncating)
    merge_final<<<BATCH, 1024>>>(out, top_out);        // A -> outputs + prep

    nms_mask<<<dim3(TOPK / 64, TOPK / 64, BATCH), 64>>>();
    nms_reduce<<<BATCH, 256>>>(keep_out);
}